// round 8
// baseline (speedup 1.0000x reference)
#include <cuda_runtime.h>
#include <cuda_bf16.h>
#include <math.h>
#include <stdint.h>

#define BB 512
#define SS 64
#define TT 32
#define VV 128
#define EE 256
#define HH 512
#define DENC 1024
#define G4H 2048
#define EOS_IDX 2
#define PCOL (HH + DENC)  /* 1536 */

// ---------------- scratch (device globals; no allocations) ----------------
__device__ __nv_bfloat16 g_encproj_bf[(size_t)BB * SS * HH];  // 32 MB (score path)
__device__ float g_pred[(size_t)BB * TT * PCOL];       // 100 MB  [h1n | context]
__device__ float g_Wc0[G4H * (DENC + HH)];             // [W_ih0[:,E:] | W_hh0] (plain)
__device__ float g_Wc1[G4H * (HH + HH)];               // [W_ih1 | W_hh1] (plain)
__device__ float g_token_gates[VV * G4H];              // per-token W_ih0[:, :E] @ emb
__device__ float g_token_preds[VV * VV];               // per-token W_out emb part + b_out
__device__ int   g_tokens[BB * TT];                    // input token per (b,t)
__device__ float g_xbuf[BB * (DENC + HH)];             // [context | h0]
__device__ float g_x1buf[BB * (HH + HH)];              // [h0n | h1]
__device__ float g_gates[BB * G4H];
__device__ float g_c0buf[BB * HH];
__device__ float g_c1buf[BB * HH];
__device__ float g_decproj[BB * HH];

__device__ __forceinline__ float sigmoid_fast(float x) {
    return __fdividef(1.0f, 1.0f + __expf(-x));
}
__device__ __forceinline__ float tanh_hw(float x) {
    float y;
    asm("tanh.approx.f32 %0, %1;" : "=f"(y) : "f"(x));
    return y;
}

__device__ __forceinline__ uint32_t f2tf32(float x) {
    uint32_t r;
    asm("cvt.rna.tf32.f32 %0, %1;" : "=r"(r) : "f"(x));
    return r;
}

__device__ __forceinline__ void mma_tf32(float* c, const uint32_t* a, const uint32_t* b) {
    asm volatile(
        "mma.sync.aligned.m16n8k8.row.col.f32.tf32.tf32.f32 "
        "{%0,%1,%2,%3},{%4,%5,%6,%7},{%8,%9},{%0,%1,%2,%3};"
        : "+f"(c[0]), "+f"(c[1]), "+f"(c[2]), "+f"(c[3])
        : "r"(a[0]), "r"(a[1]), "r"(a[2]), "r"(a[3]), "r"(b[0]), "r"(b[1]));
}

// ---------------- TF32 tensor-core NT GEMM, 2-stage double buffered ----------------
// C[M,N] = A(MxK) * B(NxK)^T  (+bias0[n]+bias1[n]+Cin[row', n]; optional += C; bf16 out)
// rowtok: if non-null, Cin row index = rowtok[row * rts] (token-indexed Cin gather).
template <int BM, int BN, int BK, int WM, int WN>
__global__ void __launch_bounds__((BM / WM) * (BN / WN) * 32, 2)
mma_nt_kernel(int M, int N, int K,
              const float* __restrict__ A, int lda,
              const float* __restrict__ B, int ldb,
              void* __restrict__ Cv, int ldc,
              const float* __restrict__ Cin, int ldcin,
              const float* __restrict__ bias0,
              const float* __restrict__ bias1,
              const int* __restrict__ rowtok, int rts,
              int accumulate, int out_bf16) {
    constexpr int WARPS_M = BM / WM, WARPS_N = BN / WN;
    constexpr int NW = WARPS_M * WARPS_N, THREADS = NW * 32;
    constexpr int MI = WM / 16, NI = WN / 8, KI = BK / 8;
    constexpr int PAD = 8;
    constexpr int A_LD4 = BM * (BK / 4) / THREADS;
    constexpr int B_LD4 = BN * (BK / 4) / THREADS;

    __shared__ uint32_t As[2][BK][BM + PAD];
    __shared__ uint32_t Bs[2][BK][BN + PAD];

    const int tid = threadIdx.x;
    const int wid = tid >> 5, lane = tid & 31;
    const int wm = (wid / WARPS_N) * WM, wn = (wid % WARPS_N) * WN;
    const int g = lane >> 2, tg = lane & 3;
    const int bm = blockIdx.y * BM, bn = blockIdx.x * BN;

    float acc[MI][NI][4];
#pragma unroll
    for (int i = 0; i < MI; i++)
#pragma unroll
        for (int j = 0; j < NI; j++)
#pragma unroll
            for (int q = 0; q < 4; q++) acc[i][j][q] = 0.0f;

    float4 ra[A_LD4], rb[B_LD4];

    auto load_tile = [&](int k0) {
#pragma unroll
        for (int i = 0; i < A_LD4; i++) {
            int idx = tid + i * THREADS;
            int m = idx / (BK / 4), kq = (idx % (BK / 4)) * 4;
            ra[i] = *(const float4*)(A + (size_t)(bm + m) * lda + k0 + kq);
        }
#pragma unroll
        for (int i = 0; i < B_LD4; i++) {
            int idx = tid + i * THREADS;
            int n = idx / (BK / 4), kq = (idx % (BK / 4)) * 4;
            rb[i] = *(const float4*)(B + (size_t)(bn + n) * ldb + k0 + kq);
        }
    };
    auto store_tile = [&](int buf) {
#pragma unroll
        for (int i = 0; i < A_LD4; i++) {
            int idx = tid + i * THREADS;
            int m = idx / (BK / 4), kq = (idx % (BK / 4)) * 4;
            As[buf][kq + 0][m] = f2tf32(ra[i].x);
            As[buf][kq + 1][m] = f2tf32(ra[i].y);
            As[buf][kq + 2][m] = f2tf32(ra[i].z);
            As[buf][kq + 3][m] = f2tf32(ra[i].w);
        }
#pragma unroll
        for (int i = 0; i < B_LD4; i++) {
            int idx = tid + i * THREADS;
            int n = idx / (BK / 4), kq = (idx % (BK / 4)) * 4;
            Bs[buf][kq + 0][n] = f2tf32(rb[i].x);
            Bs[buf][kq + 1][n] = f2tf32(rb[i].y);
            Bs[buf][kq + 2][n] = f2tf32(rb[i].z);
            Bs[buf][kq + 3][n] = f2tf32(rb[i].w);
        }
    };

    load_tile(0);
    store_tile(0);
    __syncthreads();

    int buf = 0;
    for (int k0 = 0; k0 < K; k0 += BK) {
        const bool has_next = (k0 + BK) < K;
        if (has_next) load_tile(k0 + BK);

#pragma unroll
        for (int ki = 0; ki < KI; ki++) {
            uint32_t af[MI][4];
            uint32_t bf[NI][2];
#pragma unroll
            for (int mi = 0; mi < MI; mi++) {
                int mrow = wm + mi * 16 + g;
                af[mi][0] = As[buf][ki * 8 + tg][mrow];
                af[mi][1] = As[buf][ki * 8 + tg][mrow + 8];
                af[mi][2] = As[buf][ki * 8 + tg + 4][mrow];
                af[mi][3] = As[buf][ki * 8 + tg + 4][mrow + 8];
            }
#pragma unroll
            for (int ni = 0; ni < NI; ni++) {
                int ncol = wn + ni * 8 + g;
                bf[ni][0] = Bs[buf][ki * 8 + tg][ncol];
                bf[ni][1] = Bs[buf][ki * 8 + tg + 4][ncol];
            }
#pragma unroll
            for (int mi = 0; mi < MI; mi++)
#pragma unroll
                for (int ni = 0; ni < NI; ni++) mma_tf32(acc[mi][ni], af[mi], bf[ni]);
        }

        if (has_next) store_tile(buf ^ 1);
        __syncthreads();
        buf ^= 1;
    }

    // epilogue
#pragma unroll
    for (int mi = 0; mi < MI; mi++) {
#pragma unroll
        for (int ni = 0; ni < NI; ni++) {
            const int col = bn + wn + ni * 8 + tg * 2;
#pragma unroll
            for (int half = 0; half < 2; half++) {
                const int row = bm + wm + mi * 16 + g + half * 8;
                float v0 = acc[mi][ni][half * 2 + 0];
                float v1 = acc[mi][ni][half * 2 + 1];
                if (out_bf16) {
                    __nv_bfloat162* cp =
                        (__nv_bfloat162*)((__nv_bfloat16*)Cv + (size_t)row * ldc + col);
                    *cp = __float22bfloat162_rn(make_float2(v0, v1));
                    continue;
                }
                float* C = (float*)Cv;
                if (bias0) { v0 += bias0[col]; v1 += bias0[col + 1]; }
                if (bias1) { v0 += bias1[col]; v1 += bias1[col + 1]; }
                if (Cin) {
                    const int crow = rowtok ? rowtok[row * rts] : row;
                    float2 ci = *(const float2*)(Cin + (size_t)crow * ldcin + col);
                    v0 += ci.x; v1 += ci.y;
                }
                float2* cp = (float2*)(C + (size_t)row * ldc + col);
                if (accumulate) {
                    float2 c = *cp;
                    v0 += c.x; v1 += c.y;
                }
                *cp = make_float2(v0, v1);
            }
        }
    }
}

template <int BM, int BN, int BK, int WM, int WN>
static void mgemm(int M, int N, int K,
                  const float* A, int lda, const float* B, int ldb,
                  void* C, int ldc,
                  const float* Cin = nullptr, int ldcin = 0,
                  const float* bias0 = nullptr, const float* bias1 = nullptr,
                  const int* rowtok = nullptr, int rts = 1,
                  bool accumulate = false, bool out_bf16 = false) {
    dim3 grid(N / BN, M / BM);
    mma_nt_kernel<BM, BN, BK, WM, WN><<<grid, (BM / WM) * (BN / WN) * 32>>>(
        M, N, K, A, lda, B, ldb, C, ldc, Cin, ldcin, bias0, bias1, rowtok, rts,
        accumulate ? 1 : 0, out_bf16 ? 1 : 0);
}

// ---------------- precompute kernels ----------------
__global__ void tokens_kernel(const int* __restrict__ targets, int* __restrict__ toks) {
    int idx = blockIdx.x * blockDim.x + threadIdx.x;  // B*T
    int t = idx & (TT - 1);
    int b = idx >> 5;
    toks[idx] = (t == 0) ? EOS_IDX : targets[b * TT + t - 1];
}

// plain-layout combined weights
__global__ void build_wcomb_kernel(const float* __restrict__ W_ih0,
                                   const float* __restrict__ W_hh0,
                                   const float* __restrict__ W_ih1,
                                   const float* __restrict__ W_hh1,
                                   float* __restrict__ Wc0,
                                   float* __restrict__ Wc1) {
    int idx = blockIdx.x * blockDim.x + threadIdx.x;
    const int N0 = G4H * (DENC + HH);
    const int N1 = G4H * (HH + HH);
    if (idx < N0) {
        int n = idx / (DENC + HH);
        int k = idx % (DENC + HH);
        Wc0[idx] = (k < DENC) ? W_ih0[(size_t)n * (EE + DENC) + EE + k]
                              : W_hh0[(size_t)n * HH + (k - DENC)];
    } else if (idx < N0 + N1) {
        int r = idx - N0;
        int n = r / (HH + HH);
        int k = r % (HH + HH);
        Wc1[r] = (k < HH) ? W_ih1[(size_t)n * HH + k]
                          : W_hh1[(size_t)n * HH + (k - HH)];
    }
}

__global__ void init_state_kernel(const float* __restrict__ h0,
                                  const float* __restrict__ c0,
                                  float* __restrict__ xbuf,
                                  float* __restrict__ x1buf,
                                  float* __restrict__ cb0,
                                  float* __restrict__ cb1) {
    int idx = blockIdx.x * blockDim.x + threadIdx.x;  // B*H
    int b = idx >> 9;
    int h = idx & (HH - 1);
    xbuf[(size_t)b * (DENC + HH) + DENC + h] = h0[idx];
    x1buf[(size_t)b * (HH + HH) + HH + h] = h0[(size_t)BB * HH + idx];
    cb0[idx] = c0[idx];
    cb1[idx] = c0[(size_t)BB * HH + idx];
}

// ---------------- attention (fused score/tanh + masked softmax + context) ----------------
__global__ void __launch_bounds__(256) attention_kernel(
    const __nv_bfloat16* __restrict__ enc_proj,   // (B,S,H) bf16
    const float* __restrict__ enc,        // (B,S,DENC) fp32
    const float* __restrict__ decp,       // (B,H)
    const float* __restrict__ vvec,       // (H)
    const int* __restrict__ mask,         // (B,S)
    float* __restrict__ ctx_dst1, int ld1,
    float* __restrict__ ctx_dst2, int ld2) {
    const int b = blockIdx.x;
    __shared__ float s_dp[HH];
    __shared__ float s_v[HH];
    __shared__ float s_w[SS];
    __shared__ float s_red[2];
    const int tid = threadIdx.x;
    const int warp = tid >> 5, lane = tid & 31;

    for (int i = tid; i < HH; i += 256) {
        s_dp[i] = decp[(size_t)b * HH + i];
        s_v[i] = vvec[i];
    }
    __syncthreads();

    for (int s = warp; s < SS; s += 8) {
        const __nv_bfloat162* ep =
            (const __nv_bfloat162*)(enc_proj + ((size_t)b * SS + s) * HH);
        float acc = 0.0f;
#pragma unroll 4
        for (int h2 = lane; h2 < HH / 2; h2 += 32) {
            float2 e = __bfloat1622float2(ep[h2]);
            acc += s_v[2 * h2] * tanh_hw(s_dp[2 * h2] + e.x);
            acc += s_v[2 * h2 + 1] * tanh_hw(s_dp[2 * h2 + 1] + e.y);
        }
#pragma unroll
        for (int o = 16; o; o >>= 1) acc += __shfl_xor_sync(0xffffffffu, acc, o);
        if (lane == 0) s_w[s] = mask[b * SS + s] ? acc : -1e30f;
    }
    __syncthreads();

    if (warp == 0) {
        float m = fmaxf(s_w[lane], s_w[lane + 32]);
#pragma unroll
        for (int o = 16; o; o >>= 1) m = fmaxf(m, __shfl_xor_sync(0xffffffffu, m, o));
        float sum = __expf(s_w[lane] - m) + __expf(s_w[lane + 32] - m);
#pragma unroll
        for (int o = 16; o; o >>= 1) sum += __shfl_xor_sync(0xffffffffu, sum, o);
        if (lane == 0) { s_red[0] = m; s_red[1] = sum; }
    }
    __syncthreads();
    const float m = s_red[0], inv = 1.0f / s_red[1];
    if (tid < SS) s_w[tid] = __expf(s_w[tid] - m) * inv;
    __syncthreads();

    const float* eb = enc + (size_t)b * SS * DENC;
    for (int d = tid; d < DENC; d += 256) {
        float acc = 0.0f;
#pragma unroll 8
        for (int s = 0; s < SS; s++) acc += s_w[s] * eb[(size_t)s * DENC + d];
        ctx_dst1[(size_t)b * ld1 + d] = acc;
        ctx_dst2[(size_t)b * ld2 + d] = acc;
    }
}

// ---------------- LSTM pointwise cell (plain gate layout) ----------------
__global__ void lstm_cell_kernel(const float* __restrict__ gates,  // (B,4H)
                                 float* __restrict__ c,            // (B,H) in/out
                                 float* __restrict__ hA, int ldA,
                                 float* __restrict__ hB, int ldB) {
    int idx = blockIdx.x * blockDim.x + threadIdx.x;  // B*H
    int b = idx >> 9;
    int h = idx & (HH - 1);
    const float* g = gates + (size_t)b * G4H;
    float ig = sigmoid_fast(g[h]);
    float fg = sigmoid_fast(g[HH + h]);
    float gg = tanhf(g[2 * HH + h]);
    float og = sigmoid_fast(g[3 * HH + h]);
    float cn = fg * c[idx] + ig * gg;
    c[idx] = cn;
    float hn = og * tanhf(cn);
    hA[(size_t)b * ldA + h] = hn;
    hB[(size_t)b * ldB + h] = hn;
}

// ---------------- host ----------------
extern "C" void kernel_launch(void* const* d_in, const int* in_sizes, int n_in,
                              void* d_out, int out_size) {
    const float* encoder_out = (const float*)d_in[0];
    const float* h0   = (const float*)d_in[1];
    const float* c0   = (const float*)d_in[2];
    const int*   targets = (const int*)d_in[3];
    const int*   mask    = (const int*)d_in[4];
    const float* emb   = (const float*)d_in[5];
    const float* W_enc = (const float*)d_in[6];
    const float* W_dec = (const float*)d_in[7];
    const float* vvec  = (const float*)d_in[8];
    const float* W_ih0 = (const float*)d_in[9];
    const float* W_hh0 = (const float*)d_in[10];
    const float* b_ih0 = (const float*)d_in[11];
    const float* b_hh0 = (const float*)d_in[12];
    const float* W_ih1 = (const float*)d_in[13];
    const float* W_hh1 = (const float*)d_in[14];
    const float* b_ih1 = (const float*)d_in[15];
    const float* b_hh1 = (const float*)d_in[16];
    const float* W_out = (const float*)d_in[17];
    const float* b_out = (const float*)d_in[18];
    float* out = (float*)d_out;  // (B,T,V)

    __nv_bfloat16* p_encproj_bf;
    float *p_pred, *p_Wc0, *p_Wc1, *p_tokg, *p_tokp;
    float *p_xbuf, *p_x1buf, *p_gates, *p_c0, *p_c1, *p_decproj;
    int* p_tokens;
    cudaGetSymbolAddress((void**)&p_encproj_bf, g_encproj_bf);
    cudaGetSymbolAddress((void**)&p_pred, g_pred);
    cudaGetSymbolAddress((void**)&p_Wc0, g_Wc0);
    cudaGetSymbolAddress((void**)&p_Wc1, g_Wc1);
    cudaGetSymbolAddress((void**)&p_tokg, g_token_gates);
    cudaGetSymbolAddress((void**)&p_tokp, g_token_preds);
    cudaGetSymbolAddress((void**)&p_tokens, g_tokens);
    cudaGetSymbolAddress((void**)&p_xbuf, g_xbuf);
    cudaGetSymbolAddress((void**)&p_x1buf, g_x1buf);
    cudaGetSymbolAddress((void**)&p_gates, g_gates);
    cudaGetSymbolAddress((void**)&p_c0, g_c0buf);
    cudaGetSymbolAddress((void**)&p_c1, g_c1buf);
    cudaGetSymbolAddress((void**)&p_decproj, g_decproj);

    // ---- precompute ----
    tokens_kernel<<<(BB * TT) / 256, 256>>>(targets, p_tokens);
    {
        int total = G4H * (DENC + HH) + G4H * (HH + HH);
        build_wcomb_kernel<<<(total + 255) / 256, 256>>>(W_ih0, W_hh0, W_ih1, W_hh1,
                                                         p_Wc0, p_Wc1);
    }
    init_state_kernel<<<(BB * HH) / 256, 256>>>(h0, c0, p_xbuf, p_x1buf, p_c0, p_c1);

    // token_gates (V,4H) = emb @ W_ih0[:, :E]^T
    mgemm<64, 128, 16, 32, 32>(VV, G4H, EE, emb, EE, W_ih0, EE + DENC, p_tokg, G4H);
    // token_preds (V,V) = emb @ W_out[:, H+DENC:]^T + b_out
    mgemm<64, 64, 16, 32, 16>(VV, VV, EE, emb, EE, W_out + (HH + DENC), HH + DENC + EE,
                              p_tokp, VV, nullptr, 0, b_out);
    // enc_proj -> bf16 (score path only)
    mgemm<128, 128, 16, 64, 32>(BB * SS, HH, DENC, encoder_out, DENC, W_enc, DENC,
                                p_encproj_bf, HH, nullptr, 0, nullptr, nullptr,
                                nullptr, 1, false, true);

    // ---- sequential decode ----
    for (int t = 0; t < TT; t++) {
        // dec_proj = h1 @ W_dec^T  (8 warps/CTA)
        mgemm<64, 64, 16, 32, 16>(BB, HH, HH, p_x1buf + HH, HH + HH, W_dec, HH,
                                  p_decproj, HH);

        // attention: context -> xbuf[:, :DENC] and pred[:, t, H:]
        attention_kernel<<<BB, 256>>>(p_encproj_bf, encoder_out, p_decproj, vvec, mask,
                                      p_xbuf, DENC + HH,
                                      p_pred + (size_t)t * PCOL + HH, TT * PCOL);

        // gates0 = [context|h0] @ Wc0^T + token_gates[tok(b,t)] + b_ih0 + b_hh0  (8 warps/CTA)
        mgemm<64, 128, 16, 32, 32>(BB, G4H, DENC + HH, p_xbuf, DENC + HH, p_Wc0,
                                   DENC + HH, p_gates, G4H,
                                   p_tokg, G4H, b_ih0, b_hh0,
                                   p_tokens + t, TT);
        lstm_cell_kernel<<<(BB * HH) / 256, 256>>>(p_gates, p_c0,
                                                   p_x1buf, HH + HH,
                                                   p_xbuf + DENC, DENC + HH);

        // gates1 = [h0n|h1] @ Wc1^T + b_ih1 + b_hh1  (8 warps/CTA)
        mgemm<64, 128, 16, 32, 32>(BB, G4H, HH + HH, p_x1buf, HH + HH, p_Wc1, HH + HH,
                                   p_gates, G4H, nullptr, 0, b_ih1, b_hh1);
        lstm_cell_kernel<<<(BB * HH) / 256, 256>>>(p_gates, p_c1,
                                                   p_x1buf + HH, HH + HH,
                                                   p_pred + (size_t)t * PCOL, TT * PCOL);
    }

    // logits: out = [h1n|context] @ W_out[:, :H+DENC]^T + token_preds[tok(b,t)]
    mgemm<128, 128, 16, 64, 32>(BB * TT, VV, PCOL, p_pred, PCOL, W_out, HH + DENC + EE,
                                out, VV, p_tokp, VV, nullptr, nullptr,
                                p_tokens, 1);
}